// round 13
// baseline (speedup 1.0000x reference)
#include <cuda_runtime.h>
#include <cuda_fp16.h>
#include <cstdint>

// ---------------- problem constants ----------------
constexpr int BB     = 32768;   // batch
constexpr int DD     = 128;     // input dim
constexpr int OUTF   = 192;     // n_d + n_a
constexpr int HH     = 384;     // 2*OUTF
constexpr int NSTEP  = 3;
constexpr int NDOUT  = 64;      // n_d
constexpr int SMBLK  = 1024;    // sparsemax blocks (32 rows each)
#define EPS_BN 1e-5f

// ---------------- scratch (device globals: allocation-free) ----------------
__device__ float g_xbn[BB * DD];
__device__ float g_M[BB * DD];              // only written at step 1 (read at step 2)
__device__ float g_enc[BB * 128];           // sigmoid(enc att cols), compact [BB,128]
__device__ float g_bnpart[256 * 2 * DD];
__device__ float g_bnscale[DD];
__device__ float g_bnshift[DD];
__device__ float g_losspart[NSTEP * SMBLK]; // only steps 1,2 written

// fp16 activations
__device__ __align__(128) __half g_ax[BB * DD];      // masked_x
__device__ __align__(128) __half g_ase[BB * OUTF];   // enc GLU0 out
__device__ __align__(128) __half g_asd[BB * OUTF];   // dec GLU0 out

// fp16 PERMUTED weights; row perm: n<192->2n else 2(n-192)+1
__device__ __align__(128) __half g_eW0s[NSTEP * HH * DD];
__device__ __align__(128) __half g_eW1s[NSTEP * HH * OUTF];
__device__ __align__(128) __half g_dW0s[NSTEP * HH * DD];
__device__ __align__(128) __half g_dW1s[NSTEP * HH * OUTF];

// ---------------- mma / ldmatrix / cp.async primitives ----------------
__device__ __forceinline__ void ldsm4(unsigned* r, const void* p) {
    unsigned a = (unsigned)__cvta_generic_to_shared(p);
    asm volatile("ldmatrix.sync.aligned.m8n8.x4.shared.b16 {%0,%1,%2,%3}, [%4];"
                 : "=r"(r[0]), "=r"(r[1]), "=r"(r[2]), "=r"(r[3]) : "r"(a));
}
__device__ __forceinline__ void mma16816(float* d, const unsigned* a, unsigned b0, unsigned b1) {
    asm volatile(
        "mma.sync.aligned.m16n8k16.row.col.f32.f16.f16.f32 "
        "{%0,%1,%2,%3}, {%4,%5,%6,%7}, {%8,%9}, {%0,%1,%2,%3};"
        : "+f"(d[0]), "+f"(d[1]), "+f"(d[2]), "+f"(d[3])
        : "r"(a[0]), "r"(a[1]), "r"(a[2]), "r"(a[3]), "r"(b0), "r"(b1));
}
__device__ __forceinline__ void cp16(void* sdst, const void* gsrc) {
    unsigned a = (unsigned)__cvta_generic_to_shared(sdst);
    asm volatile("cp.async.ca.shared.global [%0], [%1], 16;" :: "r"(a), "l"(gsrc));
}
__device__ __forceinline__ void cp_commit() {
    asm volatile("cp.async.commit_group;" ::: "memory");
}
__device__ __forceinline__ void cp_wait0() {
    asm volatile("cp.async.wait_group 0;" ::: "memory");
}

// ---------------- smem plan (R9-proven) ----------
// mainloop: Asm/Bsm each [2][128][40] fp16 = 40960B total
// epilogue: p_s/p_q [4][128] fp32 + sc/sh [128] fp32 (separate region)
constexpr int SM_PS      = 40960;
constexpr int SM_PQ      = SM_PS + 2048;
constexpr int SM_SC_OFF  = SM_PQ + 2048;
constexpr int SM_SH_OFF  = SM_SC_OFF + 512;
constexpr int SMEM_BYTES = SM_SH_OFF + 512;   // 46080

// ---------------- BN stats ----------------
__global__ void bn_partial_kernel(const float* __restrict__ x) {
    __shared__ float ss[256], sq[256];
    int t = threadIdx.x, blk = blockIdx.x;
    int col = t & 127, half = t >> 7;
    const float* xp = x + ((size_t)blk * 128 + half * 64) * DD + col;
    float s = 0.f, q = 0.f;
#pragma unroll 8
    for (int r = 0; r < 64; r++) { float v = xp[(size_t)r * DD]; s += v; q += v * v; }
    ss[t] = s; sq[t] = q;
    __syncthreads();
    if (t < 128) {
        g_bnpart[(blk * 2 + 0) * DD + t] = ss[t] + ss[t + 128];
        g_bnpart[(blk * 2 + 1) * DD + t] = sq[t] + sq[t + 128];
    }
}

__global__ void bn_finalize_kernel(const float* __restrict__ gam, const float* __restrict__ bet) {
    int c = threadIdx.x;
    float s = 0.f, q = 0.f;
    for (int b = 0; b < 256; b++) {
        s += g_bnpart[(b * 2 + 0) * DD + c];
        q += g_bnpart[(b * 2 + 1) * DD + c];
    }
    float mean = s / (float)BB;
    float var  = q / (float)BB - mean * mean;
    float inv  = 1.f / sqrtf(var + EPS_BN);
    float sc   = gam[c] * inv;
    g_bnscale[c] = sc;
    g_bnshift[c] = bet[c] - mean * sc;
}

// BN apply + step-0 masked_x (M == 1/128 exactly when att == 1)
__global__ void bn_apply_kernel(const float* __restrict__ x) {
    int i = blockIdx.x * blockDim.x + threadIdx.x;
    if (i >= BB * DD / 4) return;
    float4 v = ((const float4*)x)[i];
    int c = (i & 31) * 4;
    v.x = v.x * g_bnscale[c + 0] + g_bnshift[c + 0];
    v.y = v.y * g_bnscale[c + 1] + g_bnshift[c + 1];
    v.z = v.z * g_bnscale[c + 2] + g_bnshift[c + 2];
    v.w = v.w * g_bnscale[c + 3] + g_bnshift[c + 3];
    ((float4*)g_xbn)[i] = v;
    const float m = 1.f / 128.f;
    __half2 h01 = __floats2half2_rn(v.x * m, v.y * m);
    __half2 h23 = __floats2half2_rn(v.z * m, v.w * m);
    ((uint2*)g_ax)[i] = make_uint2(*(unsigned*)&h01, *(unsigned*)&h23);
}

// ---------------- merged weight convert+permute (ONE launch, all 10) --------
__global__ void wsplit_all_kernel(const float* __restrict__ eW0, const float* __restrict__ eW1,
                                  const float* __restrict__ dW0, const float* __restrict__ dW1,
                                  __half* oe0, __half* oe1, __half* od0, __half* od1) {
    int y = blockIdx.y;
    int s = y >> 2, which = y & 3;
    if (s == NSTEP - 1 && which < 2) return;   // enc weights dead at last step
    int K = (which & 1) ? OUTF : DD;
    int i = blockIdx.x * 256 + threadIdx.x;
    if (i >= HH * K) return;
    const float* src = (which == 0 ? eW0 : which == 1 ? eW1 : which == 2 ? dW0 : dW1)
                       + (size_t)s * HH * K;
    __half* dst = (which == 0 ? oe0 : which == 1 ? oe1 : which == 2 ? od0 : od1)
                  + (size_t)s * HH * K;
    int n = i / K, k = i - n * K;
    int perm = (n < OUTF) ? (2 * n) : (2 * (n - OUTF) + 1);
    dst[(size_t)perm * K + k] = __float2half(src[i]);
}

// ---------------- sparsemax (steps 1,2 only) ----------------
__global__ void sparsemax_kernel(int step) {
    __shared__ float wl[8];
    int t = threadIdx.x, lane = t & 31, w = t >> 5, blk = blockIdx.x;
    float acc = 0.f;
    for (int rr = 0; rr < 4; rr++) {
        size_t row = (size_t)blk * 32 + w * 4 + rr;
        const float* xp = g_xbn + row * DD;
        float* Mp = g_M + row * DD;
        __half* axp = g_ax + row * DD;
        const float* ep = g_enc + row * 128;   // compact att-sigmoid rows
        float z0, z1, z2, z3;
        if (step == 1) {   // previous M is the uniform constant 1/128
            const float om = 1.f - 1.f / 128.f;
            z0 = 1.3f * ep[lane]      * om;
            z1 = 1.3f * ep[lane + 32] * om;
            z2 = 1.3f * ep[lane + 64] * om;
            z3 = 1.3f * ep[lane + 96] * om;
        } else {
            z0 = 1.3f * ep[lane]      * (1.f - Mp[lane]);
            z1 = 1.3f * ep[lane + 32] * (1.f - Mp[lane + 32]);
            z2 = 1.3f * ep[lane + 64] * (1.f - Mp[lane + 64]);
            z3 = 1.3f * ep[lane + 96] * (1.f - Mp[lane + 96]);
        }
        float mx = fmaxf(fmaxf(z0, z1), fmaxf(z2, z3));
#pragma unroll
        for (int o = 16; o; o >>= 1) mx = fmaxf(mx, __shfl_xor_sync(0xffffffffu, mx, o));
        z0 -= mx; z1 -= mx; z2 -= mx; z3 -= mx;
        float sm = z0 + z1 + z2 + z3;
#pragma unroll
        for (int o = 16; o; o >>= 1) sm += __shfl_xor_sync(0xffffffffu, sm, o);
        float tau = (sm - 1.f) * (1.f / 128.f);
        int cnt = 128;
        for (int it = 0; it < 64; it++) {
            float s = 0.f; int c = 0;
            if (z0 > tau) { s += z0; c++; }
            if (z1 > tau) { s += z1; c++; }
            if (z2 > tau) { s += z2; c++; }
            if (z3 > tau) { s += z3; c++; }
#pragma unroll
            for (int o = 16; o; o >>= 1) {
                s += __shfl_xor_sync(0xffffffffu, s, o);
                c += __shfl_xor_sync(0xffffffffu, c, o);
            }
            if (c == cnt) break;
            cnt = c; tau = (s - 1.f) / (float)c;
        }
        float m[4] = {fmaxf(z0 - tau, 0.f), fmaxf(z1 - tau, 0.f),
                      fmaxf(z2 - tau, 0.f), fmaxf(z3 - tau, 0.f)};
        float rl = 0.f;
#pragma unroll
        for (int i = 0; i < 4; i++) {
            int c = lane + 32 * i;
            if (step < NSTEP - 1) Mp[c] = m[i];   // only needed by next step
            axp[c] = __float2half(m[i] * xp[c]);
            rl += m[i] * logf(m[i] + 1e-10f);
        }
#pragma unroll
        for (int o = 16; o; o >>= 1) rl += __shfl_xor_sync(0xffffffffu, rl, o);
        acc += rl;
    }
    if (lane == 0) wl[w] = acc;
    __syncthreads();
    if (t == 0) {
        float s = 0.f;
        for (int i = 0; i < 8; i++) s += wl[i];
        g_losspart[step * SMBLK + blk] = s;
    }
}

// ---------------- fused fp16 GEMM + GhostBN + GLU (R9 mainloop) --------------
// GLU1=false: blockIdx.x < enc_blocks -> enc, else dec; fp16 activation write.
// GLU1=true : blockIdx.x == 0 -> dec (sigmoid -> f_out), else enc (sigmoid -> f_enc compact).
template <int K, bool GLU1>
__global__ __launch_bounds__(256, 2) void gemm_glu_kernel(
        const __half* __restrict__ Ae, const __half* __restrict__ Ad,
        const __half* __restrict__ We, const __half* __restrict__ Wd,
        const float* __restrict__ eg, const float* __restrict__ eb,
        const float* __restrict__ dg, const float* __restrict__ db,
        __half* __restrict__ h_oute, __half* __restrict__ h_outd,
        float* __restrict__ f_enc, float* __restrict__ f_out,
        int enc_blocks) {
    extern __shared__ __align__(16) char smem[];
    __half* Asm = (__half*)smem;              // [2][128][40]
    __half* Bsm = Asm + 2 * 128 * 40;
    constexpr int T = K / 32;

    const int t = threadIdx.x;
    const int m0 = blockIdx.y * 128;
    bool is_enc; int nx;
    if (GLU1) { is_enc = (blockIdx.x > 0); nx = blockIdx.x; }
    else      { is_enc = ((int)blockIdx.x < enc_blocks); nx = is_enc ? blockIdx.x : blockIdx.x - enc_blocks; }
    const int n0 = nx * 128;
    const __half* A = is_enc ? Ae : Ad;
    const __half* W = is_enc ? We : Wd;
    const float* gam = is_enc ? eg : dg;
    const float* bet = is_enc ? eb : db;

    const int lrow = t >> 1;
    const int lcol = (t & 1) * 16;
    const __half* Ag = A + (size_t)(m0 + lrow) * K + lcol;
    const __half* Wg = W + (size_t)(n0 + lrow) * K + lcol;

    const int warp = t >> 5, lane = t & 31;
    const int wm = warp >> 1, wn = warp & 1;
    const int lr = lane & 15, lc = (lane >> 4) * 8;
    const int so = lrow * 40 + lcol;

    float d[2][8][4];
#pragma unroll
    for (int i = 0; i < 2; i++)
#pragma unroll
        for (int j = 0; j < 8; j++)
#pragma unroll
            for (int k = 0; k < 4; k++) d[i][j][k] = 0.f;

    cp16(&Asm[so], Ag);  cp16(&Asm[so + 8], Ag + 8);
    cp16(&Bsm[so], Wg);  cp16(&Bsm[so + 8], Wg + 8);
    cp_commit(); cp_wait0();
    __syncthreads();

    for (int kt = 0; kt < T; kt++) {
        const int bo = (kt & 1) * 5120;
        if (kt + 1 < T) {
            const int no = ((kt + 1) & 1) * 5120, off = (kt + 1) * 32;
            cp16(&Asm[no + so], Ag + off);  cp16(&Asm[no + so + 8], Ag + off + 8);
            cp16(&Bsm[no + so], Wg + off);  cp16(&Bsm[no + so + 8], Wg + off + 8);
            cp_commit();
        }
#pragma unroll
        for (int ks = 0; ks < 2; ks++) {
            const int krow = ks * 16 + lc;
            unsigned afr[2][4], bfr[4][4];
#pragma unroll
            for (int mf = 0; mf < 2; mf++)
                ldsm4(afr[mf], &Asm[bo + (wm * 32 + mf * 16 + lr) * 40 + krow]);
#pragma unroll
            for (int nb = 0; nb < 4; nb++)
                ldsm4(bfr[nb], &Bsm[bo + (wn * 64 + nb * 16 + lr) * 40 + krow]);
#pragma unroll
            for (int mf = 0; mf < 2; mf++)
#pragma unroll
                for (int n8 = 0; n8 < 8; n8++)
                    mma16816(d[mf][n8], afr[mf], bfr[n8 >> 1][n8 & 1], bfr[n8 >> 1][(n8 & 1) + 2]);
        }
        if (kt + 1 < T) { cp_wait0(); __syncthreads(); }
    }

    // ---- register-resident GhostBN: per-column sums via shfl + tiny smem ----
    float* p_s = (float*)(smem + SM_PS);   // [4 wm][128 cols]
    float* p_q = (float*)(smem + SM_PQ);
#pragma unroll
    for (int n8 = 0; n8 < 8; n8++) {
        float s0 = 0.f, s1 = 0.f, q0 = 0.f, q1 = 0.f;
#pragma unroll
        for (int mf = 0; mf < 2; mf++) {
            s0 += d[mf][n8][0] + d[mf][n8][2];
            s1 += d[mf][n8][1] + d[mf][n8][3];
            q0 += d[mf][n8][0] * d[mf][n8][0] + d[mf][n8][2] * d[mf][n8][2];
            q1 += d[mf][n8][1] * d[mf][n8][1] + d[mf][n8][3] * d[mf][n8][3];
        }
#pragma unroll
        for (int o = 4; o <= 16; o <<= 1) {
            s0 += __shfl_xor_sync(0xffffffffu, s0, o);
            s1 += __shfl_xor_sync(0xffffffffu, s1, o);
            q0 += __shfl_xor_sync(0xffffffffu, q0, o);
            q1 += __shfl_xor_sync(0xffffffffu, q1, o);
        }
        if (lane < 4) {
            int cc = wn * 64 + n8 * 8 + lane * 2;
            p_s[wm * 128 + cc]     = s0;  p_s[wm * 128 + cc + 1] = s1;
            p_q[wm * 128 + cc]     = q0;  p_q[wm * 128 + cc + 1] = q1;
        }
    }
    __syncthreads();

    float* scp = (float*)(smem + SM_SC_OFF);
    float* shp = (float*)(smem + SM_SH_OFF);
    if (t < 128) {
        float s = p_s[t] + p_s[128 + t] + p_s[256 + t] + p_s[384 + t];
        float q = p_q[t] + p_q[128 + t] + p_q[256 + t] + p_q[384 + t];
        float mean = s * (1.f / 128.f);
        float var  = q * (1.f / 128.f) - mean * mean;
        int ncol = n0 + t;
        int u = ncol >> 1, p = ncol & 1;
        int orig = u + p * OUTF;
        float scale = gam[orig] / sqrtf(var + EPS_BN);
        scp[t] = scale;
        shp[t] = bet[orig] - mean * scale;
    }
    __syncthreads();

    // ---- apply BN + GLU straight from accumulators ----
#pragma unroll
    for (int n8 = 0; n8 < 8; n8++) {
        int cc = wn * 64 + n8 * 8 + (lane & 3) * 2;
        float sa = scp[cc], ba = shp[cc], sg = scp[cc + 1], bg = shp[cc + 1];
        int u = nx * 64 + (cc >> 1);
#pragma unroll
        for (int mf = 0; mf < 2; mf++) {
            int r0 = m0 + wm * 32 + mf * 16 + (lane >> 2);
#pragma unroll
            for (int h = 0; h < 2; h++) {   // rows r0, r0+8
                float a = d[mf][n8][2 * h]     * sa + ba;
                float g = d[mf][n8][2 * h + 1] * sg + bg;
                float v = a * (1.f / (1.f + expf(-g)));
                size_t row = (size_t)(r0 + 8 * h);
                if (!GLU1) {
                    (is_enc ? h_oute : h_outd)[row * OUTF + u] = __float2half(v);
                } else {
                    float sig = 1.f / (1.f + expf(-v));
                    if (is_enc) f_enc[row * 128 + (u - NDOUT)] = sig;   // compact att rows
                    else        f_out[row * NDOUT + u] = sig;
                }
            }
        }
    }
}

// ---------------- loss finalize (adds analytic step-0 term) ----------------
__global__ void loss_finalize_kernel(float* __restrict__ outp) {
    __shared__ float s[256];
    int t = threadIdx.x;
    float a = 0.f;
    for (int i = t; i < 2 * SMBLK; i += 256) a += g_losspart[SMBLK + i];
    s[t] = a;
    __syncthreads();
    for (int o = 128; o; o >>= 1) {
        if (t < o) s[t] += s[t + o];
        __syncthreads();
    }
    if (t == 0) {
        float step0 = (float)BB * logf(1.f / 128.f + 1e-10f);   // uniform-M row loss
        outp[0] = (s[0] + step0) / ((float)BB * (float)NSTEP);
    }
}

// ---------------- launch ----------------
extern "C" void kernel_launch(void* const* d_in, const int* in_sizes, int n_in,
                              void* d_out, int out_size) {
    (void)in_sizes; (void)n_in;
    const float* x   = (const float*)d_in[0];
    const float* ig  = (const float*)d_in[1];
    const float* ib  = (const float*)d_in[2];
    const float* eW0 = (const float*)d_in[3];
    const float* eg0 = (const float*)d_in[4];
    const float* eb0 = (const float*)d_in[5];
    const float* eW1 = (const float*)d_in[6];
    const float* eg1 = (const float*)d_in[7];
    const float* eb1 = (const float*)d_in[8];
    const float* dW0 = (const float*)d_in[9];
    const float* dg0 = (const float*)d_in[10];
    const float* db0 = (const float*)d_in[11];
    const float* dW1 = (const float*)d_in[12];
    const float* dg1 = (const float*)d_in[13];
    const float* db1 = (const float*)d_in[14];
    float* out = (float*)d_out;

    float* p_enc;
    __half *p_ax, *p_ase, *p_asd, *p_eW0s, *p_eW1s, *p_dW0s, *p_dW1s;
    cudaGetSymbolAddress((void**)&p_enc, g_enc);
    cudaGetSymbolAddress((void**)&p_ax, g_ax);
    cudaGetSymbolAddress((void**)&p_ase, g_ase);
    cudaGetSymbolAddress((void**)&p_asd, g_asd);
    cudaGetSymbolAddress((void**)&p_eW0s, g_eW0s);
    cudaGetSymbolAddress((void**)&p_eW1s, g_eW1s);
    cudaGetSymbolAddress((void**)&p_dW0s, g_dW0s);
    cudaGetSymbolAddress((void**)&p_dW1s, g_dW1s);

    cudaFuncSetAttribute(gemm_glu_kernel<DD, false>,
                         cudaFuncAttributeMaxDynamicSharedMemorySize, SMEM_BYTES);
    cudaFuncSetAttribute(gemm_glu_kernel<OUTF, true>,
                         cudaFuncAttributeMaxDynamicSharedMemorySize, SMEM_BYTES);

    bn_partial_kernel<<<256, 256>>>(x);
    bn_finalize_kernel<<<1, DD>>>(ig, ib);
    bn_apply_kernel<<<BB * DD / 4 / 256, 256>>>(x);   // also emits step-0 masked_x fp16

    {
        dim3 gw((HH * OUTF + 255) / 256, NSTEP * 4);
        wsplit_all_kernel<<<gw, 256>>>(eW0, eW1, dW0, dW1, p_eW0s, p_eW1s, p_dW0s, p_dW1s);
    }

    for (int s = 0; s < NSTEP; s++) {
        if (s > 0) sparsemax_kernel<<<SMBLK, 256>>>(s);   // step 0 folded into bn_apply
        const bool enc_live = (s < NSTEP - 1);
        {
            dim3 gg(enc_live ? 6 : 3, BB / 128);
            gemm_glu_kernel<DD, false><<<gg, 256, SMEM_BYTES>>>(
                p_ax, p_ax,
                p_eW0s + (size_t)s * HH * DD, p_dW0s + (size_t)s * HH * DD,
                eg0 + s * HH, eb0 + s * HH, dg0 + s * HH, db0 + s * HH,
                p_ase, p_asd, nullptr, nullptr, enc_live ? 3 : 0);
        }
        {
            dim3 gg(enc_live ? 3 : 1, BB / 128);
            gemm_glu_kernel<OUTF, true><<<gg, 256, SMEM_BYTES>>>(
                p_ase, p_asd,
                p_eW1s + (size_t)s * HH * OUTF, p_dW1s + (size_t)s * HH * OUTF,
                eg1 + s * HH, eb1 + s * HH, dg1 + s * HH, db1 + s * HH,
                nullptr, nullptr, p_enc, out + (size_t)s * BB * NDOUT, 0);
        }
    }
    if (out_size > BB * NDOUT * NSTEP) {
        loss_finalize_kernel<<<1, 256>>>(out + (size_t)BB * NDOUT * NSTEP);
    }
}

// round 15
// speedup vs baseline: 1.0514x; 1.0514x over previous
#include <cuda_runtime.h>
#include <cuda_fp16.h>
#include <cstdint>

// ---------------- problem constants ----------------
constexpr int BB     = 32768;   // batch
constexpr int DD     = 128;     // input dim
constexpr int OUTF   = 192;     // n_d + n_a
constexpr int HH     = 384;     // 2*OUTF
constexpr int NSTEP  = 3;
constexpr int NDOUT  = 64;      // n_d
constexpr int SMBLK  = 1024;    // sparsemax blocks (32 rows each)
#define EPS_BN 1e-5f

// ---------------- scratch (device globals: allocation-free) ----------------
__device__ float g_xbn[BB * DD];
__device__ float g_M[BB * DD];              // only written at step 1 (read at step 2)
__device__ float g_enc[BB * OUTF];          // sigmoid(enc GLU out); cols 64..191 used
__device__ float g_bnpart[256 * 2 * DD];
__device__ float g_bnscale[DD];
__device__ float g_bnshift[DD];
__device__ float g_losspart[NSTEP * SMBLK]; // only steps 1,2 written

// fp16 activations
__device__ __align__(128) __half g_ax[BB * DD];      // masked_x
__device__ __align__(128) __half g_ase[BB * OUTF];   // enc GLU0 out
__device__ __align__(128) __half g_asd[BB * OUTF];   // dec GLU0 out

// fp16 PERMUTED weights; row perm: n<192->2n else 2(n-192)+1
__device__ __align__(128) __half g_eW0s[NSTEP * HH * DD];
__device__ __align__(128) __half g_eW1s[NSTEP * HH * OUTF];
__device__ __align__(128) __half g_dW0s[NSTEP * HH * DD];
__device__ __align__(128) __half g_dW1s[NSTEP * HH * OUTF];

// ---------------- mma / ldmatrix / cp.async primitives ----------------
__device__ __forceinline__ void ldsm4(unsigned* r, const void* p) {
    unsigned a = (unsigned)__cvta_generic_to_shared(p);
    asm volatile("ldmatrix.sync.aligned.m8n8.x4.shared.b16 {%0,%1,%2,%3}, [%4];"
                 : "=r"(r[0]), "=r"(r[1]), "=r"(r[2]), "=r"(r[3]) : "r"(a));
}
__device__ __forceinline__ void mma16816(float* d, const unsigned* a, unsigned b0, unsigned b1) {
    asm volatile(
        "mma.sync.aligned.m16n8k16.row.col.f32.f16.f16.f32 "
        "{%0,%1,%2,%3}, {%4,%5,%6,%7}, {%8,%9}, {%0,%1,%2,%3};"
        : "+f"(d[0]), "+f"(d[1]), "+f"(d[2]), "+f"(d[3])
        : "r"(a[0]), "r"(a[1]), "r"(a[2]), "r"(a[3]), "r"(b0), "r"(b1));
}
__device__ __forceinline__ void cp16(void* sdst, const void* gsrc) {
    unsigned a = (unsigned)__cvta_generic_to_shared(sdst);
    asm volatile("cp.async.cg.shared.global [%0], [%1], 16;" :: "r"(a), "l"(gsrc));
}
__device__ __forceinline__ void cp_commit() {
    asm volatile("cp.async.commit_group;" ::: "memory");
}
__device__ __forceinline__ void cp_wait0() {
    asm volatile("cp.async.wait_group 0;" ::: "memory");
}

// ---------------- smem plan ----------
// mainloop: Asm/Bsm each [2][128][40] fp16 = 40960B total
// epilogue: partial sums p_s/p_q [4][128] fp32 + sc/sh [128] fp32 (separate region)
constexpr int SM_PS      = 40960;
constexpr int SM_PQ      = SM_PS + 2048;
constexpr int SM_SC_OFF  = SM_PQ + 2048;
constexpr int SM_SH_OFF  = SM_SC_OFF + 512;
constexpr int SMEM_BYTES = SM_SH_OFF + 512;   // 46080

// ---------------- BN stats ----------------
__global__ void bn_partial_kernel(const float* __restrict__ x) {
    __shared__ float ss[256], sq[256];
    int t = threadIdx.x, blk = blockIdx.x;
    int col = t & 127, half = t >> 7;
    const float* xp = x + ((size_t)blk * 128 + half * 64) * DD + col;
    float s = 0.f, q = 0.f;
#pragma unroll 8
    for (int r = 0; r < 64; r++) { float v = xp[(size_t)r * DD]; s += v; q += v * v; }
    ss[t] = s; sq[t] = q;
    __syncthreads();
    if (t < 128) {
        g_bnpart[(blk * 2 + 0) * DD + t] = ss[t] + ss[t + 128];
        g_bnpart[(blk * 2 + 1) * DD + t] = sq[t] + sq[t + 128];
    }
}

__global__ void bn_finalize_kernel(const float* __restrict__ gam, const float* __restrict__ bet) {
    int c = threadIdx.x;
    float s = 0.f, q = 0.f;
    for (int b = 0; b < 256; b++) {
        s += g_bnpart[(b * 2 + 0) * DD + c];
        q += g_bnpart[(b * 2 + 1) * DD + c];
    }
    float mean = s / (float)BB;
    float var  = q / (float)BB - mean * mean;
    float inv  = 1.f / sqrtf(var + EPS_BN);
    float sc   = gam[c] * inv;
    g_bnscale[c] = sc;
    g_bnshift[c] = bet[c] - mean * sc;
}

// BN apply + step-0 masked_x (M == 1/128 exactly when att == 1)
__global__ void bn_apply_kernel(const float* __restrict__ x) {
    int i = blockIdx.x * blockDim.x + threadIdx.x;
    if (i >= BB * DD / 4) return;
    float4 v = ((const float4*)x)[i];
    int c = (i & 31) * 4;
    v.x = v.x * g_bnscale[c + 0] + g_bnshift[c + 0];
    v.y = v.y * g_bnscale[c + 1] + g_bnshift[c + 1];
    v.z = v.z * g_bnscale[c + 2] + g_bnshift[c + 2];
    v.w = v.w * g_bnscale[c + 3] + g_bnshift[c + 3];
    ((float4*)g_xbn)[i] = v;
    const float m = 1.f / 128.f;
    __half2 h01 = __floats2half2_rn(v.x * m, v.y * m);
    __half2 h23 = __floats2half2_rn(v.z * m, v.w * m);
    ((uint2*)g_ax)[i] = make_uint2(*(unsigned*)&h01, *(unsigned*)&h23);
}

// ---------------- merged weight convert+permute (ONE launch, all 10) --------
__global__ void wsplit_all_kernel(const float* __restrict__ eW0, const float* __restrict__ eW1,
                                  const float* __restrict__ dW0, const float* __restrict__ dW1,
                                  __half* oe0, __half* oe1, __half* od0, __half* od1) {
    int y = blockIdx.y;
    int s = y >> 2, which = y & 3;
    if (s == NSTEP - 1 && which < 2) return;   // enc weights dead at last step
    int K = (which & 1) ? OUTF : DD;
    int i = blockIdx.x * 256 + threadIdx.x;
    if (i >= HH * K) return;
    const float* src = (which == 0 ? eW0 : which == 1 ? eW1 : which == 2 ? dW0 : dW1)
                       + (size_t)s * HH * K;
    __half* dst = (which == 0 ? oe0 : which == 1 ? oe1 : which == 2 ? od0 : od1)
                  + (size_t)s * HH * K;
    int n = i / K, k = i - n * K;
    int perm = (n < OUTF) ? (2 * n) : (2 * (n - OUTF) + 1);
    dst[(size_t)perm * K + k] = __float2half(src[i]);
}

// ---------------- sparsemax (steps 1,2 only) ----------------
__global__ void sparsemax_kernel(int step) {
    __shared__ float wl[8];
    int t = threadIdx.x, lane = t & 31, w = t >> 5, blk = blockIdx.x;
    float acc = 0.f;
    for (int rr = 0; rr < 4; rr++) {
        size_t row = (size_t)blk * 32 + w * 4 + rr;
        const float* xp = g_xbn + row * DD;
        float* Mp = g_M + row * DD;
        __half* axp = g_ax + row * DD;
        const float* ep = g_enc + row * OUTF + NDOUT;
        float z0, z1, z2, z3;
        if (step == 1) {   // previous M is the uniform constant 1/128
            const float om = 1.f - 1.f / 128.f;
            z0 = 1.3f * ep[lane]      * om;
            z1 = 1.3f * ep[lane + 32] * om;
            z2 = 1.3f * ep[lane + 64] * om;
            z3 = 1.3f * ep[lane + 96] * om;
        } else {
            z0 = 1.3f * ep[lane]      * (1.f - Mp[lane]);
            z1 = 1.3f * ep[lane + 32] * (1.f - Mp[lane + 32]);
            z2 = 1.3f * ep[lane + 64] * (1.f - Mp[lane + 64]);
            z3 = 1.3f * ep[lane + 96] * (1.f - Mp[lane + 96]);
        }
        float mx = fmaxf(fmaxf(z0, z1), fmaxf(z2, z3));
#pragma unroll
        for (int o = 16; o; o >>= 1) mx = fmaxf(mx, __shfl_xor_sync(0xffffffffu, mx, o));
        z0 -= mx; z1 -= mx; z2 -= mx; z3 -= mx;
        float sm = z0 + z1 + z2 + z3;
#pragma unroll
        for (int o = 16; o; o >>= 1) sm += __shfl_xor_sync(0xffffffffu, sm, o);
        float tau = (sm - 1.f) * (1.f / 128.f);
        int cnt = 128;
        for (int it = 0; it < 64; it++) {
            float s = 0.f; int c = 0;
            if (z0 > tau) { s += z0; c++; }
            if (z1 > tau) { s += z1; c++; }
            if (z2 > tau) { s += z2; c++; }
            if (z3 > tau) { s += z3; c++; }
#pragma unroll
            for (int o = 16; o; o >>= 1) {
                s += __shfl_xor_sync(0xffffffffu, s, o);
                c += __shfl_xor_sync(0xffffffffu, c, o);
            }
            if (c == cnt) break;
            cnt = c; tau = (s - 1.f) / (float)c;
        }
        float m[4] = {fmaxf(z0 - tau, 0.f), fmaxf(z1 - tau, 0.f),
                      fmaxf(z2 - tau, 0.f), fmaxf(z3 - tau, 0.f)};
        float rl = 0.f;
#pragma unroll
        for (int i = 0; i < 4; i++) {
            int c = lane + 32 * i;
            if (step < NSTEP - 1) Mp[c] = m[i];   // only needed by next step
            axp[c] = __float2half(m[i] * xp[c]);
            rl += m[i] * logf(m[i] + 1e-10f);
        }
#pragma unroll
        for (int o = 16; o; o >>= 1) rl += __shfl_xor_sync(0xffffffffu, rl, o);
        acc += rl;
    }
    if (lane == 0) wl[w] = acc;
    __syncthreads();
    if (t == 0) {
        float s = 0.f;
        for (int i = 0; i < 8; i++) s += wl[i];
        g_losspart[step * SMBLK + blk] = s;
    }
}

// ---------------- fused fp16 GEMM + GhostBN + GLU (register epilogue) --------
// GLU1=false: blockIdx.x < enc_blocks -> enc, else dec; fp16 activation write.
// GLU1=true : blockIdx.x == 0 -> dec (sigmoid -> f_out), else enc (sigmoid -> f_enc).
template <int K, bool GLU1>
__global__ __launch_bounds__(256, 2) void gemm_glu_kernel(
        const __half* __restrict__ Ae, const __half* __restrict__ Ad,
        const __half* __restrict__ We, const __half* __restrict__ Wd,
        const float* __restrict__ eg, const float* __restrict__ eb,
        const float* __restrict__ dg, const float* __restrict__ db,
        __half* __restrict__ h_oute, __half* __restrict__ h_outd,
        float* __restrict__ f_enc, float* __restrict__ f_out,
        int enc_blocks) {
    extern __shared__ __align__(16) char smem[];
    __half* Asm = (__half*)smem;              // [2][128][40]
    __half* Bsm = Asm + 2 * 128 * 40;
    constexpr int T = K / 32;

    const int t = threadIdx.x;
    const int m0 = blockIdx.y * 128;
    bool is_enc; int nx;
    if (GLU1) { is_enc = (blockIdx.x > 0); nx = blockIdx.x; }
    else      { is_enc = ((int)blockIdx.x < enc_blocks); nx = is_enc ? blockIdx.x : blockIdx.x - enc_blocks; }
    const int n0 = nx * 128;
    const __half* A = is_enc ? Ae : Ad;
    const __half* W = is_enc ? We : Wd;
    const float* gam = is_enc ? eg : dg;
    const float* bet = is_enc ? eb : db;

    const int lrow = t >> 1;
    const int lcol = (t & 1) * 16;
    const __half* Ag = A + (size_t)(m0 + lrow) * K + lcol;
    const __half* Wg = W + (size_t)(n0 + lrow) * K + lcol;

    const int warp = t >> 5, lane = t & 31;
    const int wm = warp >> 1, wn = warp & 1;
    const int lr = lane & 15, lc = (lane >> 4) * 8;
    const int so = lrow * 40 + lcol;

    float d[2][8][4];
#pragma unroll
    for (int i = 0; i < 2; i++)
#pragma unroll
        for (int j = 0; j < 8; j++)
#pragma unroll
            for (int k = 0; k < 4; k++) d[i][j][k] = 0.f;

    cp16(&Asm[so], Ag);  cp16(&Asm[so + 8], Ag + 8);
    cp16(&Bsm[so], Wg);  cp16(&Bsm[so + 8], Wg + 8);
    cp_commit(); cp_wait0();
    __syncthreads();

    for (int kt = 0; kt < T; kt++) {
        const int bo = (kt & 1) * 5120;
        if (kt + 1 < T) {
            const int no = ((kt + 1) & 1) * 5120, off = (kt + 1) * 32;
            cp16(&Asm[no + so], Ag + off);  cp16(&Asm[no + so + 8], Ag + off + 8);
            cp16(&Bsm[no + so], Wg + off);  cp16(&Bsm[no + so + 8], Wg + off + 8);
            cp_commit();
        }
#pragma unroll
        for (int ks = 0; ks < 2; ks++) {
            const int krow = ks * 16 + lc;
            unsigned afr[2][4], bfr[4][4];
#pragma unroll
            for (int mf = 0; mf < 2; mf++)
                ldsm4(afr[mf], &Asm[bo + (wm * 32 + mf * 16 + lr) * 40 + krow]);
#pragma unroll
            for (int nb = 0; nb < 4; nb++)
                ldsm4(bfr[nb], &Bsm[bo + (wn * 64 + nb * 16 + lr) * 40 + krow]);
#pragma unroll
            for (int mf = 0; mf < 2; mf++)
#pragma unroll
                for (int n8 = 0; n8 < 8; n8++)
                    mma16816(d[mf][n8], afr[mf], bfr[n8 >> 1][n8 & 1], bfr[n8 >> 1][(n8 & 1) + 2]);
        }
        if (kt + 1 < T) { cp_wait0(); __syncthreads(); }
    }

    // ---- register-resident GhostBN: per-column sums via shfl + tiny smem ----
    float* p_s = (float*)(smem + SM_PS);   // [4 wm][128 cols]
    float* p_q = (float*)(smem + SM_PQ);
#pragma unroll
    for (int n8 = 0; n8 < 8; n8++) {
        float s0 = 0.f, s1 = 0.f, q0 = 0.f, q1 = 0.f;
#pragma unroll
        for (int mf = 0; mf < 2; mf++) {
            s0 += d[mf][n8][0] + d[mf][n8][2];
            s1 += d[mf][n8][1] + d[mf][n8][3];
            q0 += d[mf][n8][0] * d[mf][n8][0] + d[mf][n8][2] * d[mf][n8][2];
            q1 += d[mf][n8][1] * d[mf][n8][1] + d[mf][n8][3] * d[mf][n8][3];
        }
#pragma unroll
        for (int o = 4; o <= 16; o <<= 1) {
            s0 += __shfl_xor_sync(0xffffffffu, s0, o);
            s1 += __shfl_xor_sync(0xffffffffu, s1, o);
            q0 += __shfl_xor_sync(0xffffffffu, q0, o);
            q1 += __shfl_xor_sync(0xffffffffu, q1, o);
        }
        if (lane < 4) {
            int cc = wn * 64 + n8 * 8 + lane * 2;
            p_s[wm * 128 + cc]     = s0;  p_s[wm * 128 + cc + 1] = s1;
            p_q[wm * 128 + cc]     = q0;  p_q[wm * 128 + cc + 1] = q1;
        }
    }
    __syncthreads();

    float* scp = (float*)(smem + SM_SC_OFF);
    float* shp = (float*)(smem + SM_SH_OFF);
    if (t < 128) {
        float s = p_s[t] + p_s[128 + t] + p_s[256 + t] + p_s[384 + t];
        float q = p_q[t] + p_q[128 + t] + p_q[256 + t] + p_q[384 + t];
        float mean = s * (1.f / 128.f);
        float var  = q * (1.f / 128.f) - mean * mean;
        int ncol = n0 + t;
        int u = ncol >> 1, p = ncol & 1;
        int orig = u + p * OUTF;
        float scale = gam[orig] / sqrtf(var + EPS_BN);
        scp[t] = scale;
        shp[t] = bet[orig] - mean * scale;
    }
    __syncthreads();

    // ---- apply BN + GLU straight from accumulators ----
#pragma unroll
    for (int n8 = 0; n8 < 8; n8++) {
        int cc = wn * 64 + n8 * 8 + (lane & 3) * 2;
        float sa = scp[cc], ba = shp[cc], sg = scp[cc + 1], bg = shp[cc + 1];
        int u = nx * 64 + (cc >> 1);
#pragma unroll
        for (int mf = 0; mf < 2; mf++) {
            int r0 = m0 + wm * 32 + mf * 16 + (lane >> 2);
#pragma unroll
            for (int h = 0; h < 2; h++) {   // rows r0, r0+8
                float a = d[mf][n8][2 * h]     * sa + ba;
                float g = d[mf][n8][2 * h + 1] * sg + bg;
                float v = a * (1.f / (1.f + expf(-g)));
                size_t row = (size_t)(r0 + 8 * h);
                if (!GLU1) {
                    (is_enc ? h_oute : h_outd)[row * OUTF + u] = __float2half(v);
                } else {
                    float sig = 1.f / (1.f + expf(-v));
                    if (is_enc) f_enc[row * OUTF + u] = sig;
                    else        f_out[row * NDOUT + u] = sig;
                }
            }
        }
    }
}

// ---------------- loss finalize (adds analytic step-0 term) ----------------
__global__ void loss_finalize_kernel(float* __restrict__ outp) {
    __shared__ float s[256];
    int t = threadIdx.x;
    float a = 0.f;
    for (int i = t; i < 2 * SMBLK; i += 256) a += g_losspart[SMBLK + i];
    s[t] = a;
    __syncthreads();
    for (int o = 128; o; o >>= 1) {
        if (t < o) s[t] += s[t + o];
        __syncthreads();
    }
    if (t == 0) {
        float step0 = (float)BB * logf(1.f / 128.f + 1e-10f);   // uniform-M row loss
        outp[0] = (s[0] + step0) / ((float)BB * (float)NSTEP);
    }
}

// ---------------- launch ----------------
extern "C" void kernel_launch(void* const* d_in, const int* in_sizes, int n_in,
                              void* d_out, int out_size) {
    (void)in_sizes; (void)n_in;
    const float* x   = (const float*)d_in[0];
    const float* ig  = (const float*)d_in[1];
    const float* ib  = (const float*)d_in[2];
    const float* eW0 = (const float*)d_in[3];
    const float* eg0 = (const float*)d_in[4];
    const float* eb0 = (const float*)d_in[5];
    const float* eW1 = (const float*)d_in[6];
    const float* eg1 = (const float*)d_in[7];
    const float* eb1 = (const float*)d_in[8];
    const float* dW0 = (const float*)d_in[9];
    const float* dg0 = (const float*)d_in[10];
    const float* db0 = (const float*)d_in[11];
    const float* dW1 = (const float*)d_in[12];
    const float* dg1 = (const float*)d_in[13];
    const float* db1 = (const float*)d_in[14];
    float* out = (float*)d_out;

    float* p_enc;
    __half *p_ax, *p_ase, *p_asd, *p_eW0s, *p_eW1s, *p_dW0s, *p_dW1s;
    cudaGetSymbolAddress((void**)&p_enc, g_enc);
    cudaGetSymbolAddress((void**)&p_ax, g_ax);
    cudaGetSymbolAddress((void**)&p_ase, g_ase);
    cudaGetSymbolAddress((void**)&p_asd, g_asd);
    cudaGetSymbolAddress((void**)&p_eW0s, g_eW0s);
    cudaGetSymbolAddress((void**)&p_eW1s, g_eW1s);
    cudaGetSymbolAddress((void**)&p_dW0s, g_dW0s);
    cudaGetSymbolAddress((void**)&p_dW1s, g_dW1s);

    cudaFuncSetAttribute(gemm_glu_kernel<DD, false>,
                         cudaFuncAttributeMaxDynamicSharedMemorySize, SMEM_BYTES);
    cudaFuncSetAttribute(gemm_glu_kernel<OUTF, true>,
                         cudaFuncAttributeMaxDynamicSharedMemorySize, SMEM_BYTES);

    bn_partial_kernel<<<256, 256>>>(x);
    bn_finalize_kernel<<<1, DD>>>(ig, ib);
    bn_apply_kernel<<<BB * DD / 4 / 256, 256>>>(x);   // also emits step-0 masked_x fp16

    {
        dim3 gw((HH * OUTF + 255) / 256, NSTEP * 4);
        wsplit_all_kernel<<<gw, 256>>>(eW0, eW1, dW0, dW1, p_eW0s, p_eW1s, p_dW0s, p_dW1s);
    }

    for (int s = 0; s < NSTEP; s++) {
        if (s > 0) sparsemax_kernel<<<SMBLK, 256>>>(s);   // step 0 folded into bn_apply
        const bool enc_live = (s < NSTEP - 1);
        {
            dim3 gg(enc_live ? 6 : 3, BB / 128);
            gemm_glu_kernel<DD, false><<<gg, 256, SMEM_BYTES>>>(
                p_ax, p_ax,
                p_eW0s + (size_t)s * HH * DD, p_dW0s + (size_t)s * HH * DD,
                eg0 + s * HH, eb0 + s * HH, dg0 + s * HH, db0 + s * HH,
                p_ase, p_asd, nullptr, nullptr, enc_live ? 3 : 0);
        }
        {
            dim3 gg(enc_live ? 3 : 1, BB / 128);
            gemm_glu_kernel<OUTF, true><<<gg, 256, SMEM_BYTES>>>(
                p_ase, p_asd,
                p_eW1s + (size_t)s * HH * OUTF, p_dW1s + (size_t)s * HH * OUTF,
                eg1 + s * HH, eb1 + s * HH, dg1 + s * HH, db1 + s * HH,
                nullptr, nullptr, p_enc, out + (size_t)s * BB * NDOUT, 0);
        }
    }
    if (out_size > BB * NDOUT * NSTEP) {
        loss_finalize_kernel<<<1, 256>>>(out + (size_t)BB * NDOUT * NSTEP);
    }
}